// round 15
// baseline (speedup 1.0000x reference)
#include <cuda_runtime.h>
#include <cuda_bf16.h>
#include <stdint.h>

#define NCORR    10000
#define MPAD     10048                 // 157*64
#define DEM_LEN  20480
#define NCHUNK_M 157
#define CHUNK_M  64
#define NPAD     10240
#define NTILES   (10 * 3 * NCHUNK_M)   // 4710
#define NPIX     16384
#define MTHETA   1184                  // θ-grid; ×4 n-chunks = 4736 tasks = #decode warps
#define NBLK     148
#define NSLICE   79                    // 79*128 = 10112 >= NCORR
#define LOG2E    1.4426950408889634
#define RSQRT2   0.70710678118654752f
#define RSQRT6   0.40824829046386302f
#define SQRT2F   1.41421356237309505f
#define TWOPI    6.283185307179586476925286766559

typedef unsigned long long ull;

__device__ __forceinline__ ull pk(float lo, float hi) {
    ull r; asm("mov.b64 %0, {%1,%2};" : "=l"(r) : "f"(lo), "f"(hi)); return r;
}
__device__ __forceinline__ void upk(ull v, float& lo, float& hi) {
    asm("mov.b64 {%0,%1}, %2;" : "=f"(lo), "=f"(hi) : "l"(v));
}
__device__ __forceinline__ ull f2mul(ull a, ull b) {
    ull d; asm("mul.rn.f32x2 %0, %1, %2;" : "=l"(d) : "l"(a), "l"(b)); return d;
}
__device__ __forceinline__ ull f2add(ull a, ull b) {
    ull d; asm("add.rn.f32x2 %0, %1, %2;" : "=l"(d) : "l"(a), "l"(b)); return d;
}
__device__ __forceinline__ ull f2fma(ull a, ull b, ull c) {
    ull d; asm("fma.rn.f32x2 %0, %1, %2, %3;" : "=l"(d) : "l"(a), "l"(b), "l"(c)); return d;
}
__device__ __forceinline__ float ex2(float x) {
    float r; asm("ex2.approx.f32 %0, %1;" : "=f"(r) : "f"(x)); return r;
}

// ---------------- device scratch ----------------
__device__ float  g_modT[3][MPAD];
__device__ float  g_demT2[3][DEM_LEN];
__device__ float  g_part[3][NCHUNK_M][NPAD];
__device__ float  g_raw[3][NCORR];
__device__ double g_s6[6][5];                         // column-sum partials
__device__ double g_bs1[3][NSLICE], g_bs2[3][NSLICE]; // corr moment partials
__device__ __align__(16) float2 g_ps[MTHETA][4];      // per-(theta, n-chunk) (S, W)
__device__ int    g_tilectr;                          // corr tile counter

// ======== kernel 1: prep (transpose+dup+pad) + fp64 col-sum partials ========
__global__ void __launch_bounds__(1024) prep_kernel(const float* __restrict__ Mod,
                                                    const float* __restrict__ Dem) {
    const int tid = threadIdx.x, bid = blockIdx.x;
    if (bid < 60) {                               // 60*1024 = 61440 = 3*DEM_LEN
        const int idx = bid * 1024 + tid;
        if (idx == 0) g_tilectr = 0;
        const int k = idx / DEM_LEN, j = idx % DEM_LEN;
        if (j < NCORR) {
            g_modT[k][j] = Mod[j * 3 + k];
            float d = Dem[j * 3 + k];
            g_demT2[k][j]         = d;
            g_demT2[k][j + NCORR] = d;
        } else {
            if (j < MPAD)       g_modT[k][j]  = 0.f;
            if (j >= 2 * NCORR) g_demT2[k][j] = 0.f;
        }
    } else {                                      // 30 blocks: 6 cols x 5 chunks (fp64)
        __shared__ double sh[1024];
        const int b = bid - 60;
        const int col = b / 5, chunk = b % 5;
        const int k = col % 3;
        const float* src = (col < 3) ? Mod : Dem;
        const int base = chunk * 2000;
        double s = 0.0;
        for (int i = tid; i < 2000; i += 1024) s += (double)src[(base + i) * 3 + k];
        sh[tid] = s; __syncthreads();
        for (int o = 512; o; o >>= 1) {
            if (tid < o) sh[tid] += sh[tid + o];
            __syncthreads();
        }
        if (tid == 0) g_s6[col][chunk] = sh[0];
    }
}

// ======== kernel 2: correlation — dual-copy smem (aligned + shifted), no pk/upk ========
// Thread t owns outputs n = n0+8t..+7 as 4 f32x2 pairs. For each m-group of 4:
//   m=4g   : pair_j += mv0 * A-pair at offset 2j      (PA0..PA3)
//   m=4g+1 : pair_j += mv1 * S-pair at offset 2j      (PS0..PS3; S = dem shifted +1)
//   m=4g+2 : pair_j += mv2 * A-pair at offset 2j+2    (PA1..PA4)
//   m=4g+3 : pair_j += mv3 * S-pair at offset 2j+2    (PS1..PS4)
// Window slides 2 pairs per group; one LDS.128 per copy per group.
__global__ void __launch_bounds__(128, 8) corr_kernel() {
    __shared__ __align__(16) float sdemA[1120];
    __shared__ __align__(16) float sdemS[1120];
    __shared__ ull smod[64];
    __shared__ int s_tile;
    const int tid = threadIdx.x;
    while (true) {
        if (tid == 0) s_tile = atomicAdd(&g_tilectr, 1);
        __syncthreads();
        const int tile = s_tile;
        if (tile >= NTILES) break;
        const int nslice = tile % 10, rem = tile / 10;
        const int k = rem % 3, mc = rem / 3;
        const int n0 = nslice * 1024, m0 = mc * CHUNK_M;

        if (tid < CHUNK_M) { float v = g_modT[k][m0 + tid]; smod[tid] = pk(v, v); }
        for (int i = tid; i < 1104; i += 128) {
            sdemA[i] = g_demT2[k][m0 + n0 + i];
            sdemS[i] = g_demT2[k][m0 + n0 + i + 1];
        }
        __syncthreads();

        ull a0 = 0ull, a1 = 0ull, a2 = 0ull, a3 = 0ull;
        const ulonglong2* qpA = reinterpret_cast<const ulonglong2*>(&sdemA[8 * tid]);
        const ulonglong2* qpS = reinterpret_cast<const ulonglong2*>(&sdemS[8 * tid]);
        ulonglong2 ta0 = qpA[0], ta1 = qpA[1], ta2 = qpA[2];
        ulonglong2 ts0 = qpS[0], ts1 = qpS[1], ts2 = qpS[2];
        ull PA0 = ta0.x, PA1 = ta0.y, PA2 = ta1.x, PA3 = ta1.y, PA4 = ta2.x, PA5 = ta2.y;
        ull PS0 = ts0.x, PS1 = ts0.y, PS2 = ts1.x, PS3 = ts1.y, PS4 = ts2.x, PS5 = ts2.y;

#pragma unroll 4
        for (int g = 0; g < 16; g++) {           // 16 groups x 4 m = 64 m
            ull mv0 = smod[4 * g], mv1 = smod[4 * g + 1],
                mv2 = smod[4 * g + 2], mv3 = smod[4 * g + 3];
            a0 = f2fma(mv0, PA0, a0); a1 = f2fma(mv0, PA1, a1);
            a2 = f2fma(mv0, PA2, a2); a3 = f2fma(mv0, PA3, a3);
            a0 = f2fma(mv1, PS0, a0); a1 = f2fma(mv1, PS1, a1);
            a2 = f2fma(mv1, PS2, a2); a3 = f2fma(mv1, PS3, a3);
            a0 = f2fma(mv2, PA1, a0); a1 = f2fma(mv2, PA2, a1);
            a2 = f2fma(mv2, PA3, a2); a3 = f2fma(mv2, PA4, a3);
            a0 = f2fma(mv3, PS1, a0); a1 = f2fma(mv3, PS2, a1);
            a2 = f2fma(mv3, PS3, a2); a3 = f2fma(mv3, PS4, a3);
            // slide 2 pairs
            PA0 = PA2; PA1 = PA3; PA2 = PA4; PA3 = PA5;
            PS0 = PS2; PS1 = PS3; PS2 = PS4; PS3 = PS5;
            ulonglong2 na = qpA[g + 3], ns = qpS[g + 3];
            PA4 = na.x; PA5 = na.y;
            PS4 = ns.x; PS5 = ns.y;
        }
        {
            float o0, o1, o2, o3, o4, o5, o6, o7;
            upk(a0, o0, o1); upk(a1, o2, o3); upk(a2, o4, o5); upk(a3, o6, o7);
            float* dst = &g_part[k][mc][n0 + 8 * tid];
            *reinterpret_cast<float4*>(dst)     = make_float4(o0, o1, o2, o3);
            *reinterpret_cast<float4*>(dst + 4) = make_float4(o4, o5, o6, o7);
        }
        __syncthreads();
    }
}

// ======== kernel 3: fold m-chunk partials + fp64 moments (237 blocks x 128) ========
__global__ void __launch_bounds__(128) fold_kernel() {
    const int tid = threadIdx.x, bid = blockIdx.x;
    const int k = bid / NSLICE, slice = bid % NSLICE;
    const int n = slice * 128 + tid;
    float acc = 0.f;
#pragma unroll 8
    for (int c = 0; c < NCHUNK_M; c++) acc += g_part[k][c][n];
    double x = 0.0;
    if (n < NCORR) { g_raw[k][n] = acc; x = (double)acc; }
    double s = x, sq = x * x;
#pragma unroll
    for (int o = 16; o; o >>= 1) {
        s  += __shfl_xor_sync(0xffffffffu, s,  o);
        sq += __shfl_xor_sync(0xffffffffu, sq, o);
    }
    __shared__ double sm1[4], sm2[4];
    if ((tid & 31) == 0) { sm1[tid >> 5] = s; sm2[tid >> 5] = sq; }
    __syncthreads();
    if (tid == 0) {
        g_bs1[k][slice] = sm1[0] + sm1[1] + sm1[2] + sm1[3];
        g_bs2[k][slice] = sm2[0] + sm2[1] + sm2[2] + sm2[3];
    }
}

// ======== kernel 4: stats + build templates + theta decode (148 x 1024) ========
__global__ void __launch_bounds__(1024, 1) decode_kernel() {
    extern __shared__ __align__(16) char smem_raw[];
    const int tid = threadIdx.x, bid = blockIdx.x;

    // --- stats (every block, redundant + identical) ---
    __shared__ float sh_scale[3], sh_mean[3];
    {
        const int w = tid >> 5, lane = tid & 31;
        __shared__ double sh_msum[3];
        if (w < 3) {
            double s = (lane < 5) ? g_s6[w][lane] : 0.0;
#pragma unroll
            for (int o = 16; o; o >>= 1) s += __shfl_xor_sync(0xffffffffu, s, o);
            if (lane == 0) sh_msum[w] = s;
        }
        __syncthreads();
        if (w < 3) {                               // fold 79 moment partials per k
            double s1 = g_bs1[w][lane] + g_bs1[w][lane + 32];
            double s2 = g_bs2[w][lane] + g_bs2[w][lane + 32];
            if (lane < 15) { s1 += g_bs1[w][lane + 64]; s2 += g_bs2[w][lane + 64]; }
#pragma unroll
            for (int o = 16; o; o >>= 1) {
                s1 += __shfl_xor_sync(0xffffffffu, s1, o);
                s2 += __shfl_xor_sync(0xffffffffu, s2, o);
            }
            if (lane == 0) {
                double mean = s1 / NCORR;
                double var  = (s2 - s1 * s1 / NCORR) / (NCORR - 1);
                double sgn  = (sh_msum[w] < 0.0) ? -1.0 : 1.0;
                sh_scale[w] = (float)(sgn * LOG2E / sqrt(var));
                sh_mean[w]  = (float)mean;
            }
        }
    }
    __syncthreads();

    // --- build SoA templates (u, v) into smem ---
    float* s_u = reinterpret_cast<float*>(smem_raw);
    float* s_v = s_u + 10048;
    {
        const float sc0 = sh_scale[0], sc1 = sh_scale[1], sc2 = sh_scale[2];
        const float mv0 = sh_mean[0],  mv1 = sh_mean[1],  mv2 = sh_mean[2];
        for (int n = tid; n < NCORR; n += 1024) {
            float c0 = sc0 * (g_raw[0][n] - mv0);
            float c1 = sc1 * (g_raw[1][n] - mv1);
            float c2 = sc2 * (g_raw[2][n] - mv2);
            s_u[n] = (c0 - c1) * RSQRT2;
            s_v[n] = (c0 + c1 - 2.f * c2) * RSQRT6;
        }
    }
    __syncthreads();

    // --- theta-grid decode: exactly 1 task per warp ---
    {
        const int lane = tid & 31;
        const int task = bid * 32 + (tid >> 5);
        const int j = task >> 2, chunk = task & 3;
        const int base = chunk * 2500;
        float sn_, cs_;
        sincosf((float)((double)j * (TWOPI / MTHETA)), &sn_, &cs_);
        const float p = SQRT2F * cs_, q = SQRT2F * sn_;
        const ull pp = pk(p, p), qq = pk(q, q);
        const ull c128 = pk(128.f, 128.f);

        ull sA = 0ull, sB = 0ull, wA = 0ull, wB = 0ull;
        const int nb = base + 4 * lane;
        ull nfA = pk((float)nb, (float)(nb + 1));
        ull nfB = pk((float)(nb + 2), (float)(nb + 3));
        const ulonglong2* pu = reinterpret_cast<const ulonglong2*>(&s_u[nb]);
        const ulonglong2* pv = reinterpret_cast<const ulonglong2*>(&s_v[nb]);

#pragma unroll 4
        for (int it = 0; it < 19; it++) {         // 19*128 = 2432 of 2500
            ulonglong2 U = pu[it * 32];
            ulonglong2 V = pv[it * 32];
            ull zA = f2fma(pp, U.x, f2mul(qq, V.x));
            ull zB = f2fma(pp, U.y, f2mul(qq, V.y));
            float a, b;
            upk(zA, a, b); ull eA = pk(ex2(a), ex2(b));
            upk(zB, a, b); ull eB = pk(ex2(a), ex2(b));
            sA = f2add(sA, eA);  sB = f2add(sB, eB);
            wA = f2fma(eA, nfA, wA); wB = f2fma(eB, nfB, wB);
            nfA = f2add(nfA, c128);  nfB = f2add(nfB, c128);
        }
        if (lane < 17) {                          // tail: 68 samples
            const int n = base + 2432 + 4 * lane;
            ulonglong2 U = *reinterpret_cast<const ulonglong2*>(&s_u[n]);
            ulonglong2 V = *reinterpret_cast<const ulonglong2*>(&s_v[n]);
            ull ntA = pk((float)n, (float)(n + 1));
            ull ntB = pk((float)(n + 2), (float)(n + 3));
            ull zA = f2fma(pp, U.x, f2mul(qq, V.x));
            ull zB = f2fma(pp, U.y, f2mul(qq, V.y));
            float a, b;
            upk(zA, a, b); ull eA = pk(ex2(a), ex2(b));
            upk(zB, a, b); ull eB = pk(ex2(a), ex2(b));
            sA = f2add(sA, eA);  sB = f2add(sB, eB);
            wA = f2fma(eA, ntA, wA); wB = f2fma(eB, ntB, wB);
        }
        float a, b, s, w;
        ull st = f2add(sA, sB), wt = f2add(wA, wB);
        upk(st, a, b); s = a + b;
        upk(wt, a, b); w = a + b;
#pragma unroll
        for (int o = 16; o; o >>= 1) {
            s += __shfl_xor_sync(0xffffffffu, s, o);
            w += __shfl_xor_sync(0xffffffffu, w, o);
        }
        if (lane == 0) g_ps[j][chunk] = make_float2(s, w);
    }
}

// ======== kernel 5: gather per pixel (atan2 + lerp) ========
__global__ void __launch_bounds__(1024) gather_kernel(const float* __restrict__ gt,
                                                      float* __restrict__ out) {
    __shared__ float sh_amb[3];
    const int tid = threadIdx.x;
    if (tid < 3) {
        double s = 0.0;
#pragma unroll
        for (int c = 0; c < 5; c++) s += g_s6[3 + tid][c];
        sh_amb[tid] = (float)(1.0e6 * s);
    }
    __syncthreads();
    const float amb0 = sh_amb[0], amb1 = sh_amb[1], amb2 = sh_amb[2];
    const float inv_dt = (float)(MTHETA / TWOPI);
    const int px = blockIdx.x * 1024 + tid;
    if (px < NPIX) {
        int idx = (int)rintf(gt[px]);
        idx = min(max(idx, 0), NCORR - 1);
        float x = g_raw[0][idx] + amb0;
        float y = g_raw[1][idx] + amb1;
        float z = g_raw[2][idx] + amb2;
        float pv = (x - y);
        float qv = (x + y - 2.f * z) * (RSQRT6 / RSQRT2);
        float th = atan2f(qv, pv);
        if (th < 0.f) th += (float)TWOPI;
        float g = th * inv_dt;
        int j0 = (int)g;
        float f = g - (float)j0;
        if (j0 >= MTHETA) j0 -= MTHETA;
        int j1 = j0 + 1; if (j1 >= MTHETA) j1 -= MTHETA;
        const float4* q0 = reinterpret_cast<const float4*>(&g_ps[j0][0]);
        const float4* q1 = reinterpret_cast<const float4*>(&g_ps[j1][0]);
        float4 u0 = q0[0], u1 = q0[1];
        float4 v0 = q1[0], v1 = q1[1];
        float S0 = u0.x + u0.z + u1.x + u1.z;
        float W0 = u0.y + u0.w + u1.y + u1.w;
        float S1 = v0.x + v0.z + v1.x + v1.z;
        float W1 = v0.y + v0.w + v1.y + v1.w;
        float F0 = W0 / S0, F1 = W1 / S1;
        out[px] = fmaf(f, F1 - F0, F0);
    }
}

extern "C" void kernel_launch(void* const* d_in, const int* in_sizes, int n_in,
                              void* d_out, int out_size) {
    const float* gt  = (const float*)d_in[0];
    const float* Mod = (const float*)d_in[1];
    const float* Dem = (const float*)d_in[2];
    float* out = (float*)d_out;

    prep_kernel<<<90, 1024>>>(Mod, Dem);
    corr_kernel<<<1184, 128>>>();
    fold_kernel<<<3 * NSLICE, 128>>>();

    int smem = 98304;   // templates 80.4KB
    cudaFuncSetAttribute(decode_kernel, cudaFuncAttributeMaxDynamicSharedMemorySize, smem);
    decode_kernel<<<NBLK, 1024, smem>>>();

    gather_kernel<<<16, 1024>>>(gt, out);
}

// round 16
// speedup vs baseline: 1.2858x; 1.2858x over previous
#include <cuda_runtime.h>
#include <cuda_bf16.h>
#include <stdint.h>

#define NCORR    10000
#define MPAD     10048                 // 157*64
#define DEM_LEN  20480
#define NCHUNK_M 157
#define CHUNK_M  64
#define NPAD     10240
#define NTILES   (10 * 3 * NCHUNK_M)   // 4710
#define NPIX     16384
#define MTHETA   296                   // θ-grid; ×16 n-chunks = 4736 tasks = #tail warps
#define NCHT     16                    // n-chunks per theta (625 samples each)
#define NBLK     148
#define NSLICE   79
#define LOG2E    1.4426950408889634
#define RSQRT2   0.70710678118654752f
#define RSQRT6   0.40824829046386302f
#define SQRT2F   1.41421356237309505f
#define TWOPI    6.283185307179586476925286766559

typedef unsigned long long ull;

__device__ __forceinline__ ull pk(float lo, float hi) {
    ull r; asm("mov.b64 %0, {%1,%2};" : "=l"(r) : "f"(lo), "f"(hi)); return r;
}
__device__ __forceinline__ void upk(ull v, float& lo, float& hi) {
    asm("mov.b64 {%0,%1}, %2;" : "=f"(lo), "=f"(hi) : "l"(v));
}
__device__ __forceinline__ ull f2fma(ull a, ull b, ull c) {
    ull d; asm("fma.rn.f32x2 %0, %1, %2, %3;" : "=l"(d) : "l"(a), "l"(b), "l"(c)); return d;
}
__device__ __forceinline__ float ex2(float x) {
    float r; asm("ex2.approx.f32 %0, %1;" : "=f"(r) : "f"(x)); return r;
}

// ---------------- device scratch ----------------
__device__ float  g_modT[3][MPAD];
__device__ float  g_demT2[3][DEM_LEN];
__device__ float  g_part[3][NCHUNK_M][NPAD];
__device__ float  g_raw[3][NCORR];
__device__ double g_s6[6][5];                         // column-sum partials
__device__ double g_bs1[3][NSLICE], g_bs2[3][NSLICE]; // corr moment partials
__device__ __align__(16) float2 g_ps[MTHETA][NCHT];   // per-(theta, n-chunk) (S, W)
__device__ int    g_tilectr;
__device__ int    g_sync2;                            // tail barrier (148), monotonic

__device__ __forceinline__ void grid_sync_n(int* ctr, int nblk) {
    __syncthreads();
    if (threadIdx.x == 0) {
        __threadfence();
        int t = atomicAdd(ctr, 1);
        int target = (t / nblk + 1) * nblk;
        while (*(volatile int*)ctr < target) {}
        __threadfence();
    }
    __syncthreads();
}

// ======== kernel 1: prep (transpose+dup+pad) + fp64 col-sum partials ========
__global__ void __launch_bounds__(1024) prep_kernel(const float* __restrict__ Mod,
                                                    const float* __restrict__ Dem) {
    const int tid = threadIdx.x, bid = blockIdx.x;
    if (bid < 60) {
        const int idx = bid * 1024 + tid;
        if (idx == 0) g_tilectr = 0;
        const int k = idx / DEM_LEN, j = idx % DEM_LEN;
        if (j < NCORR) {
            g_modT[k][j] = Mod[j * 3 + k];
            float d = Dem[j * 3 + k];
            g_demT2[k][j]         = d;
            g_demT2[k][j + NCORR] = d;
        } else {
            if (j < MPAD)       g_modT[k][j]  = 0.f;
            if (j >= 2 * NCORR) g_demT2[k][j] = 0.f;
        }
    } else {
        __shared__ double sh[1024];
        const int b = bid - 60;
        const int col = b / 5, chunk = b % 5;
        const int k = col % 3;
        const float* src = (col < 3) ? Mod : Dem;
        const int base = chunk * 2000;
        double s = 0.0;
        for (int i = tid; i < 2000; i += 1024) s += (double)src[(base + i) * 3 + k];
        sh[tid] = s; __syncthreads();
        for (int o = 512; o; o >>= 1) {
            if (tid < o) sh[tid] += sh[tid + o];
            __syncthreads();
        }
        if (tid == 0) g_s6[col][chunk] = sh[0];
    }
}

// ======== kernel 2: correlation — R13 version (proven ~16us) ========
__global__ void __launch_bounds__(128) corr_kernel() {
    __shared__ __align__(16) float sdem[1120];
    __shared__ ull smod[64];
    __shared__ int s_tile;
    const int stid = threadIdx.x;
    while (true) {
        if (stid == 0) s_tile = atomicAdd(&g_tilectr, 1);
        __syncthreads();
        const int tile = s_tile;
        if (tile >= NTILES) break;
        const int nslice = tile % 10, rem = tile / 10;
        const int k = rem % 3, mc = rem / 3;
        const int n0 = nslice * 1024, m0 = mc * CHUNK_M;

        if (stid < CHUNK_M) { float v = g_modT[k][m0 + stid]; smod[stid] = pk(v, v); }
        for (int i = stid; i < 1104; i += 128) sdem[i] = g_demT2[k][m0 + n0 + i];
        __syncthreads();

        ull a0 = 0ull, a1 = 0ull, a2 = 0ull, a3 = 0ull;
        const ulonglong2* qp = reinterpret_cast<const ulonglong2*>(&sdem[8 * stid]);
        ulonglong2 qa = qp[0], qb = qp[1], qc = qp[2];
        ull P0 = qa.x, P1 = qa.y, P2 = qb.x, P3 = qb.y, P4 = qc.x, P5 = qc.y;
#pragma unroll 4
        for (int g = 0; g < 16; g++) {
            ull mv0 = smod[4 * g], mv1 = smod[4 * g + 1],
                mv2 = smod[4 * g + 2], mv3 = smod[4 * g + 3];
            float w0, w1, w2, w3, w4, w5, w6, w7, w8, w9, w10, w11;
            upk(P0, w0, w1); upk(P1, w2, w3); upk(P2, w4, w5);
            upk(P3, w6, w7); upk(P4, w8, w9); upk(P5, w10, w11);
            ull B0 = pk(w1, w2), B1 = pk(w3, w4), B2 = pk(w5, w6),
                B3 = pk(w7, w8), B4 = pk(w9, w10);
            a0 = f2fma(mv0, P0, a0); a1 = f2fma(mv0, P1, a1);
            a2 = f2fma(mv0, P2, a2); a3 = f2fma(mv0, P3, a3);
            a0 = f2fma(mv1, B0, a0); a1 = f2fma(mv1, B1, a1);
            a2 = f2fma(mv1, B2, a2); a3 = f2fma(mv1, B3, a3);
            a0 = f2fma(mv2, P1, a0); a1 = f2fma(mv2, P2, a1);
            a2 = f2fma(mv2, P3, a2); a3 = f2fma(mv2, P4, a3);
            a0 = f2fma(mv3, B1, a0); a1 = f2fma(mv3, B2, a1);
            a2 = f2fma(mv3, B3, a2); a3 = f2fma(mv3, B4, a3);
            P0 = P2; P1 = P3; P2 = P4; P3 = P5;
            ulonglong2 qn = qp[g + 3];
            P4 = qn.x; P5 = qn.y;
        }
        {
            float o0, o1, o2, o3, o4, o5, o6, o7;
            upk(a0, o0, o1); upk(a1, o2, o3); upk(a2, o4, o5); upk(a3, o6, o7);
            float* dst = &g_part[k][mc][n0 + 8 * stid];
            *reinterpret_cast<float4*>(dst)     = make_float4(o0, o1, o2, o3);
            *reinterpret_cast<float4*>(dst + 4) = make_float4(o4, o5, o6, o7);
        }
        __syncthreads();
    }
}

// ======== kernel 3: fold + stats + build + theta decode + gather ========
__global__ void __launch_bounds__(1024, 1)
tail_kernel(const float* __restrict__ gt, float* __restrict__ out) {
    extern __shared__ __align__(16) char smem_raw[];
    const int tid = threadIdx.x, bid = blockIdx.x;

    // --- phase C: fold m-chunk partials (blocks 0..119) + fp64 moments ---
    if (bid < 120) {
        float* comb = reinterpret_cast<float*>(smem_raw);     // [4][256]
        __shared__ double sm1[8], sm2[8];
        const int k = bid / 40, rem = bid % 40;
        const int n0 = rem * 256;
        const int r = tid >> 8, j = tid & 255;
        const int n = n0 + j;
        {
            float acc = 0.f;
            const int c0 = r * 40, cend = (r < 3) ? c0 + 40 : NCHUNK_M;
            for (int c = c0; c < cend; c++) acc += g_part[k][c][n];
            comb[r * 256 + j] = acc;
        }
        __syncthreads();
        if (tid < 256) {
            float acc = comb[tid] + comb[256 + tid] + comb[512 + tid] + comb[768 + tid];
            double x = 0.0;
            if (n0 + tid < NCORR) { g_raw[k][n0 + tid] = acc; x = (double)acc; }
            double s = x, sq = x * x;
#pragma unroll
            for (int o = 16; o; o >>= 1) {
                s  += __shfl_xor_sync(0xffffffffu, s,  o);
                sq += __shfl_xor_sync(0xffffffffu, sq, o);
            }
            if ((tid & 31) == 0) { sm1[tid >> 5] = s; sm2[tid >> 5] = sq; }
        }
        __syncthreads();
        if (tid < 32) {
            double s  = (tid < 8) ? sm1[tid] : 0.0;
            double sq = (tid < 8) ? sm2[tid] : 0.0;
#pragma unroll
            for (int o = 16; o; o >>= 1) {
                s  += __shfl_xor_sync(0xffffffffu, s,  o);
                sq += __shfl_xor_sync(0xffffffffu, sq, o);
            }
            if (tid == 0) { g_bs1[k][tid] = s; }  // placeholder overwritten below
            if (tid == 0) { g_bs1[k][rem] = s; g_bs2[k][rem] = sq; }
        }
    }
    grid_sync_n(&g_sync2, NBLK);

    // --- phase D: every block folds stats redundantly ---
    __shared__ float sh_scale[3], sh_mean[3], sh_amb[3];
    __shared__ double sh_sums6[6];
    {
        const int w = tid >> 5, lane = tid & 31;
        if (w < 6) {
            double s = (lane < 5) ? g_s6[w][lane] : 0.0;
#pragma unroll
            for (int o = 16; o; o >>= 1) s += __shfl_xor_sync(0xffffffffu, s, o);
            if (lane == 0) sh_sums6[w] = s;
        }
        __syncthreads();
        if (w < 3) {                               // fold 40 moment partials per k
            double s1 = (lane < 40) ? g_bs1[w][lane] : 0.0;
            double s2 = (lane < 40) ? g_bs2[w][lane] : 0.0;
            if (lane < 8) { s1 += g_bs1[w][lane + 32]; s2 += g_bs2[w][lane + 32]; }
#pragma unroll
            for (int o = 16; o; o >>= 1) {
                s1 += __shfl_xor_sync(0xffffffffu, s1, o);
                s2 += __shfl_xor_sync(0xffffffffu, s2, o);
            }
            if (lane == 0) {
                double mean = s1 / NCORR;
                double var  = (s2 - s1 * s1 / NCORR) / (NCORR - 1);
                double sgn  = (sh_sums6[w] < 0.0) ? -1.0 : 1.0;
                sh_scale[w] = (float)(sgn * LOG2E / sqrt(var));
                sh_mean[w]  = (float)mean;
            }
        }
        if (tid >= 96 && tid < 99) sh_amb[tid - 96] = (float)(1.0e6 * sh_sums6[3 + (tid - 96)]);
    }
    __syncthreads();

    // --- phase E: build SoA templates (u, v) into smem ---
    float* s_u = reinterpret_cast<float*>(smem_raw);
    float* s_v = s_u + 10048;
    {
        const float sc0 = sh_scale[0], sc1 = sh_scale[1], sc2 = sh_scale[2];
        const float mv0 = sh_mean[0],  mv1 = sh_mean[1],  mv2 = sh_mean[2];
        for (int n = tid; n < NCORR; n += 1024) {
            float c0 = sc0 * (g_raw[0][n] - mv0);
            float c1 = sc1 * (g_raw[1][n] - mv1);
            float c2 = sc2 * (g_raw[2][n] - mv2);
            s_u[n] = (c0 - c1) * RSQRT2;
            s_v[n] = (c0 + c1 - 2.f * c2) * RSQRT6;
        }
    }
    __syncthreads();

    // --- phase F: theta-grid decode — 1 task per warp; task = (theta j, chunk of 625) ---
    {
        const int lane = tid & 31;
        const int task = bid * 32 + (tid >> 5);   // 0..4735
        const int j = task >> 4, chunk = task & 15;
        const int base = chunk * 625;
        float sn_, cs_;
        sincosf((float)((double)j * (TWOPI / MTHETA)), &sn_, &cs_);
        const float p = SQRT2F * cs_, q = SQRT2F * sn_;

        float s = 0.f, w = 0.f;
        float nf = (float)(base + lane);
        for (int n = base + lane; n < base + 625; n += 32) {
            float z = fmaf(p, s_u[n], q * s_v[n]);
            float e = ex2(z);
            s += e;
            w = fmaf(e, nf, w);
            nf += 32.f;
        }
#pragma unroll
        for (int o = 16; o; o >>= 1) {
            s += __shfl_xor_sync(0xffffffffu, s, o);
            w += __shfl_xor_sync(0xffffffffu, w, o);
        }
        if (lane == 0) g_ps[j][chunk] = make_float2(s, w);
    }
    grid_sync_n(&g_sync2, NBLK);

    // --- phase G: gather per pixel (atan2 + lerp over 16 chunk partials) ---
    {
        const float amb0 = sh_amb[0], amb1 = sh_amb[1], amb2 = sh_amb[2];
        const float inv_dt = (float)(MTHETA / TWOPI);
        const int px = bid * 1024 + tid;
        if (px < NPIX) {
            int idx = (int)rintf(gt[px]);
            idx = min(max(idx, 0), NCORR - 1);
            float x = __ldcg(&g_raw[0][idx]) + amb0;
            float y = __ldcg(&g_raw[1][idx]) + amb1;
            float z = __ldcg(&g_raw[2][idx]) + amb2;
            float pv = (x - y);
            float qv = (x + y - 2.f * z) * (RSQRT6 / RSQRT2);
            float th = atan2f(qv, pv);
            if (th < 0.f) th += (float)TWOPI;
            float g = th * inv_dt;
            int j0 = (int)g;
            float f = g - (float)j0;
            if (j0 >= MTHETA) j0 -= MTHETA;
            int j1 = j0 + 1; if (j1 >= MTHETA) j1 -= MTHETA;
            const float4* q0 = reinterpret_cast<const float4*>(&g_ps[j0][0]);
            const float4* q1 = reinterpret_cast<const float4*>(&g_ps[j1][0]);
            float S0 = 0.f, W0 = 0.f, S1 = 0.f, W1 = 0.f;
#pragma unroll
            for (int c = 0; c < 8; c++) {          // 16 float2 = 8 float4 per theta
                float4 a = __ldcg(&q0[c]);
                float4 b = __ldcg(&q1[c]);
                S0 += a.x + a.z;  W0 += a.y + a.w;
                S1 += b.x + b.z;  W1 += b.y + b.w;
            }
            float F0 = W0 / S0, F1 = W1 / S1;
            out[px] = fmaf(f, F1 - F0, F0);
        }
    }
}

extern "C" void kernel_launch(void* const* d_in, const int* in_sizes, int n_in,
                              void* d_out, int out_size) {
    const float* gt  = (const float*)d_in[0];
    const float* Mod = (const float*)d_in[1];
    const float* Dem = (const float*)d_in[2];
    float* out = (float*)d_out;

    prep_kernel<<<90, 1024>>>(Mod, Dem);
    corr_kernel<<<1184, 128>>>();

    int smem = 98304;   // templates 80.4KB; 148 blocks -> 1/SM, spin-sync residency
    cudaFuncSetAttribute(tail_kernel, cudaFuncAttributeMaxDynamicSharedMemorySize, smem);
    tail_kernel<<<NBLK, 1024, smem>>>(gt, out);
}

// round 17
// speedup vs baseline: 1.3547x; 1.0536x over previous
#include <cuda_runtime.h>
#include <cuda_bf16.h>
#include <stdint.h>

#define NCORR    10000
#define CHUNK_M  64
#define NCHUNK_M 157
#define NPAD     10240
#define NTILES   (10 * 3 * NCHUNK_M)   // 4710
#define NPIX     16384
#define MTHETA   1184                  // θ-grid; ×4 n-chunks = 4736 tasks = #tail warps
#define NBLK     148
#define NBLK2    1184
#define LOG2E    1.4426950408889634
#define RSQRT2   0.70710678118654752f
#define RSQRT6   0.40824829046386302f
#define SQRT2F   1.41421356237309505f
#define TWOPI    6.283185307179586476925286766559

typedef unsigned long long ull;

__device__ __forceinline__ ull pk(float lo, float hi) {
    ull r; asm("mov.b64 %0, {%1,%2};" : "=l"(r) : "f"(lo), "f"(hi)); return r;
}
__device__ __forceinline__ void upk(ull v, float& lo, float& hi) {
    asm("mov.b64 {%0,%1}, %2;" : "=f"(lo), "=f"(hi) : "l"(v));
}
__device__ __forceinline__ ull f2mul(ull a, ull b) {
    ull d; asm("mul.rn.f32x2 %0, %1, %2;" : "=l"(d) : "l"(a), "l"(b)); return d;
}
__device__ __forceinline__ ull f2add(ull a, ull b) {
    ull d; asm("add.rn.f32x2 %0, %1, %2;" : "=l"(d) : "l"(a), "l"(b)); return d;
}
__device__ __forceinline__ ull f2fma(ull a, ull b, ull c) {
    ull d; asm("fma.rn.f32x2 %0, %1, %2, %3;" : "=l"(d) : "l"(a), "l"(b), "l"(c)); return d;
}
__device__ __forceinline__ float ex2(float x) {
    float r; asm("ex2.approx.f32 %0, %1;" : "=f"(r) : "f"(x)); return r;
}

// ---------------- device scratch ----------------
__device__ float  g_part[3][NCHUNK_M][NPAD];
__device__ float  g_raw[3][NCORR];
__device__ double g_s6[6][4];                    // column-sum partials (24 blocks)
__device__ double g_bs1[3][40], g_bs2[3][40];    // corr moment partials
__device__ __align__(16) float2 g_ps[MTHETA][4]; // per-(theta, n-chunk) (S, W)
__device__ int    g_sync2;                       // tail barrier (148), monotonic

__device__ __forceinline__ void grid_sync_n(int* ctr, int nblk) {
    __syncthreads();
    if (threadIdx.x == 0) {
        __threadfence();
        int t = atomicAdd(ctr, 1);
        int target = (t / nblk + 1) * nblk;
        while (*(volatile int*)ctr < target) {}
        __threadfence();
    }
    __syncthreads();
}

// ======== kernel 1: correlation — static tiles, direct global reads ========
// Tile t = (n-slice 1024, k, m-chunk 64); block b owns t = b, b+1184, b+2368, b+3552.
// Loads transpose Mod/Dem (stride-3) on the fly; circular wrap via 2 cond-subtracts.
// Blocks 1158..1181 (3 tiles each) also compute the six fp64 column sums first.
__global__ void __launch_bounds__(128) corr_kernel(const float* __restrict__ Mod,
                                                   const float* __restrict__ Dem) {
    __shared__ __align__(16) float sdem[1120];
    __shared__ ull smod[64];
    const int tid = threadIdx.x, bid = blockIdx.x;

    if (bid >= 1158 && bid < 1182) {              // 24 blocks: 6 cols x 4 chunks (fp64)
        __shared__ double sh[128];
        const int b = bid - 1158;
        const int col = b / 4, chunk = b % 4;
        const int k = col % 3;
        const float* src = (col < 3) ? Mod : Dem;
        const int base = chunk * 2500;
        double s = 0.0;
        for (int i = tid; i < 2500; i += 128) s += (double)src[(base + i) * 3 + k];
        sh[tid] = s; __syncthreads();
        for (int o = 64; o; o >>= 1) {
            if (tid < o) sh[tid] += sh[tid + o];
            __syncthreads();
        }
        if (tid == 0) g_s6[col][chunk] = sh[0];
        __syncthreads();
    }

#pragma unroll 1
    for (int tile = bid; tile < NTILES; tile += NBLK2) {
        const int nslice = tile % 10, rem = tile / 10;
        const int k = rem % 3, mc = rem / 3;
        const int n0 = nslice * 1024, m0 = mc * CHUNK_M;

        if (tid < CHUNK_M) {
            const int m = m0 + tid;
            float v = (m < NCORR) ? Mod[m * 3 + k] : 0.f;   // zero m-pad
            smod[tid] = pk(v, v);
        }
        for (int i = tid; i < 1104; i += 128) {
            int j = m0 + n0 + i;                             // < 20304
            if (j >= NCORR) j -= NCORR;
            if (j >= NCORR) j -= NCORR;
            sdem[i] = Dem[j * 3 + k];
        }
        __syncthreads();

        ull a0 = 0ull, a1 = 0ull, a2 = 0ull, a3 = 0ull;
        const ulonglong2* qp = reinterpret_cast<const ulonglong2*>(&sdem[8 * tid]);
        ulonglong2 qa = qp[0], qb = qp[1], qc = qp[2];
        ull P0 = qa.x, P1 = qa.y, P2 = qb.x, P3 = qb.y, P4 = qc.x, P5 = qc.y;
#pragma unroll 4
        for (int g = 0; g < 16; g++) {            // 16 groups x 4 m = 64 m
            ull mv0 = smod[4 * g], mv1 = smod[4 * g + 1],
                mv2 = smod[4 * g + 2], mv3 = smod[4 * g + 3];
            float w0, w1, w2, w3, w4, w5, w6, w7, w8, w9, w10, w11;
            upk(P0, w0, w1); upk(P1, w2, w3); upk(P2, w4, w5);
            upk(P3, w6, w7); upk(P4, w8, w9); upk(P5, w10, w11);
            ull B0 = pk(w1, w2), B1 = pk(w3, w4), B2 = pk(w5, w6),
                B3 = pk(w7, w8), B4 = pk(w9, w10);
            a0 = f2fma(mv0, P0, a0); a1 = f2fma(mv0, P1, a1);
            a2 = f2fma(mv0, P2, a2); a3 = f2fma(mv0, P3, a3);
            a0 = f2fma(mv1, B0, a0); a1 = f2fma(mv1, B1, a1);
            a2 = f2fma(mv1, B2, a2); a3 = f2fma(mv1, B3, a3);
            a0 = f2fma(mv2, P1, a0); a1 = f2fma(mv2, P2, a1);
            a2 = f2fma(mv2, P3, a2); a3 = f2fma(mv2, P4, a3);
            a0 = f2fma(mv3, B1, a0); a1 = f2fma(mv3, B2, a1);
            a2 = f2fma(mv3, B3, a2); a3 = f2fma(mv3, B4, a3);
            P0 = P2; P1 = P3; P2 = P4; P3 = P5;
            ulonglong2 qn = qp[g + 3];
            P4 = qn.x; P5 = qn.y;
        }
        {
            float o0, o1, o2, o3, o4, o5, o6, o7;
            upk(a0, o0, o1); upk(a1, o2, o3); upk(a2, o4, o5); upk(a3, o6, o7);
            float* dst = &g_part[k][mc][n0 + 8 * tid];
            *reinterpret_cast<float4*>(dst)     = make_float4(o0, o1, o2, o3);
            *reinterpret_cast<float4*>(dst + 4) = make_float4(o4, o5, o6, o7);
        }
        __syncthreads();
    }
}

// ======== kernel 2: fold + stats + build + theta decode + gather (R13 tail) ========
__global__ void __launch_bounds__(1024, 1)
tail_kernel(const float* __restrict__ gt, float* __restrict__ out) {
    extern __shared__ __align__(16) char smem_raw[];
    const int tid = threadIdx.x, bid = blockIdx.x;

    // --- phase C: fold m-chunk partials (blocks 0..119) + fp64 moments ---
    if (bid < 120) {
        float* comb = reinterpret_cast<float*>(smem_raw);     // [4][256]
        __shared__ double sm1[8], sm2[8];
        const int k = bid / 40, rem = bid % 40;
        const int n0 = rem * 256;
        const int r = tid >> 8, j = tid & 255;
        const int n = n0 + j;
        {
            float acc = 0.f;
            const int c0 = r * 40, cend = (r < 3) ? c0 + 40 : NCHUNK_M;
            for (int c = c0; c < cend; c++) acc += g_part[k][c][n];
            comb[r * 256 + j] = acc;
        }
        __syncthreads();
        if (tid < 256) {
            float acc = comb[tid] + comb[256 + tid] + comb[512 + tid] + comb[768 + tid];
            double x = 0.0;
            if (n0 + tid < NCORR) { g_raw[k][n0 + tid] = acc; x = (double)acc; }
            double s = x, sq = x * x;
#pragma unroll
            for (int o = 16; o; o >>= 1) {
                s  += __shfl_xor_sync(0xffffffffu, s,  o);
                sq += __shfl_xor_sync(0xffffffffu, sq, o);
            }
            if ((tid & 31) == 0) { sm1[tid >> 5] = s; sm2[tid >> 5] = sq; }
        }
        __syncthreads();
        if (tid < 32) {
            double s  = (tid < 8) ? sm1[tid] : 0.0;
            double sq = (tid < 8) ? sm2[tid] : 0.0;
#pragma unroll
            for (int o = 16; o; o >>= 1) {
                s  += __shfl_xor_sync(0xffffffffu, s,  o);
                sq += __shfl_xor_sync(0xffffffffu, sq, o);
            }
            if (tid == 0) { g_bs1[k][rem] = s; g_bs2[k][rem] = sq; }
        }
    }
    grid_sync_n(&g_sync2, NBLK);

    // --- phase D: every block folds stats redundantly ---
    __shared__ float sh_scale[3], sh_mean[3], sh_amb[3];
    __shared__ double sh_sums6[6];
    {
        const int w = tid >> 5, lane = tid & 31;
        if (w < 6) {
            double s = (lane < 4) ? g_s6[w][lane] : 0.0;
#pragma unroll
            for (int o = 16; o; o >>= 1) s += __shfl_xor_sync(0xffffffffu, s, o);
            if (lane == 0) sh_sums6[w] = s;
        }
        __syncthreads();
        if (w < 3) {                               // fold 40 moment partials per k
            double s1 = (lane < 40) ? g_bs1[w][lane] : 0.0;
            double s2 = (lane < 40) ? g_bs2[w][lane] : 0.0;
            if (lane < 8) { s1 += g_bs1[w][lane + 32]; s2 += g_bs2[w][lane + 32]; }
#pragma unroll
            for (int o = 16; o; o >>= 1) {
                s1 += __shfl_xor_sync(0xffffffffu, s1, o);
                s2 += __shfl_xor_sync(0xffffffffu, s2, o);
            }
            if (lane == 0) {
                double mean = s1 / NCORR;
                double var  = (s2 - s1 * s1 / NCORR) / (NCORR - 1);
                double sgn  = (sh_sums6[w] < 0.0) ? -1.0 : 1.0;
                sh_scale[w] = (float)(sgn * LOG2E / sqrt(var));
                sh_mean[w]  = (float)mean;
            }
        }
        if (tid >= 96 && tid < 99) sh_amb[tid - 96] = (float)(1.0e6 * sh_sums6[3 + (tid - 96)]);
    }
    __syncthreads();

    // --- phase E: build SoA templates (u, v) into smem ---
    float* s_u = reinterpret_cast<float*>(smem_raw);
    float* s_v = s_u + 10048;
    {
        const float sc0 = sh_scale[0], sc1 = sh_scale[1], sc2 = sh_scale[2];
        const float mv0 = sh_mean[0],  mv1 = sh_mean[1],  mv2 = sh_mean[2];
        for (int n = tid; n < NCORR; n += 1024) {
            float c0 = sc0 * (g_raw[0][n] - mv0);
            float c1 = sc1 * (g_raw[1][n] - mv1);
            float c2 = sc2 * (g_raw[2][n] - mv2);
            s_u[n] = (c0 - c1) * RSQRT2;
            s_v[n] = (c0 + c1 - 2.f * c2) * RSQRT6;
        }
    }
    __syncthreads();

    // --- phase F: theta-grid decode — exactly 1 task per warp (packed f32x2) ---
    {
        const int lane = tid & 31;
        const int task = bid * 32 + (tid >> 5);
        const int j = task >> 2, chunk = task & 3;
        const int base = chunk * 2500;
        float sn_, cs_;
        sincosf((float)((double)j * (TWOPI / MTHETA)), &sn_, &cs_);
        const float p = SQRT2F * cs_, q = SQRT2F * sn_;
        const ull pp = pk(p, p), qq = pk(q, q);
        const ull c128 = pk(128.f, 128.f);

        ull sA = 0ull, sB = 0ull, wA = 0ull, wB = 0ull;
        const int nb = base + 4 * lane;
        ull nfA = pk((float)nb, (float)(nb + 1));
        ull nfB = pk((float)(nb + 2), (float)(nb + 3));
        const ulonglong2* pu = reinterpret_cast<const ulonglong2*>(&s_u[nb]);
        const ulonglong2* pv = reinterpret_cast<const ulonglong2*>(&s_v[nb]);

#pragma unroll 4
        for (int it = 0; it < 19; it++) {         // 19*128 = 2432 of 2500
            ulonglong2 U = pu[it * 32];
            ulonglong2 V = pv[it * 32];
            ull zA = f2fma(pp, U.x, f2mul(qq, V.x));
            ull zB = f2fma(pp, U.y, f2mul(qq, V.y));
            float a, b;
            upk(zA, a, b); ull eA = pk(ex2(a), ex2(b));
            upk(zB, a, b); ull eB = pk(ex2(a), ex2(b));
            sA = f2add(sA, eA);  sB = f2add(sB, eB);
            wA = f2fma(eA, nfA, wA); wB = f2fma(eB, nfB, wB);
            nfA = f2add(nfA, c128);  nfB = f2add(nfB, c128);
        }
        if (lane < 17) {                          // tail: 68 samples
            const int n = base + 2432 + 4 * lane;
            ulonglong2 U = *reinterpret_cast<const ulonglong2*>(&s_u[n]);
            ulonglong2 V = *reinterpret_cast<const ulonglong2*>(&s_v[n]);
            ull ntA = pk((float)n, (float)(n + 1));
            ull ntB = pk((float)(n + 2), (float)(n + 3));
            ull zA = f2fma(pp, U.x, f2mul(qq, V.x));
            ull zB = f2fma(pp, U.y, f2mul(qq, V.y));
            float a, b;
            upk(zA, a, b); ull eA = pk(ex2(a), ex2(b));
            upk(zB, a, b); ull eB = pk(ex2(a), ex2(b));
            sA = f2add(sA, eA);  sB = f2add(sB, eB);
            wA = f2fma(eA, ntA, wA); wB = f2fma(eB, ntB, wB);
        }
        float a, b, s, w;
        ull st = f2add(sA, sB), wt = f2add(wA, wB);
        upk(st, a, b); s = a + b;
        upk(wt, a, b); w = a + b;
#pragma unroll
        for (int o = 16; o; o >>= 1) {
            s += __shfl_xor_sync(0xffffffffu, s, o);
            w += __shfl_xor_sync(0xffffffffu, w, o);
        }
        if (lane == 0) g_ps[j][chunk] = make_float2(s, w);
    }
    grid_sync_n(&g_sync2, NBLK);

    // --- phase G: gather per pixel (atan2 + lerp) ---
    {
        const float amb0 = sh_amb[0], amb1 = sh_amb[1], amb2 = sh_amb[2];
        const float inv_dt = (float)(MTHETA / TWOPI);
        const int px = bid * 1024 + tid;
        if (px < NPIX) {
            int idx = (int)rintf(gt[px]);
            idx = min(max(idx, 0), NCORR - 1);
            float x = __ldcg(&g_raw[0][idx]) + amb0;
            float y = __ldcg(&g_raw[1][idx]) + amb1;
            float z = __ldcg(&g_raw[2][idx]) + amb2;
            float pv = (x - y);
            float qv = (x + y - 2.f * z) * (RSQRT6 / RSQRT2);
            float th = atan2f(qv, pv);
            if (th < 0.f) th += (float)TWOPI;
            float g = th * inv_dt;
            int j0 = (int)g;
            float f = g - (float)j0;
            if (j0 >= MTHETA) j0 -= MTHETA;
            int j1 = j0 + 1; if (j1 >= MTHETA) j1 -= MTHETA;
            const float4* q0 = reinterpret_cast<const float4*>(&g_ps[j0][0]);
            const float4* q1 = reinterpret_cast<const float4*>(&g_ps[j1][0]);
            float4 u0 = __ldcg(&q0[0]), u1 = __ldcg(&q0[1]);
            float4 v0 = __ldcg(&q1[0]), v1 = __ldcg(&q1[1]);
            float S0 = u0.x + u0.z + u1.x + u1.z;
            float W0 = u0.y + u0.w + u1.y + u1.w;
            float S1 = v0.x + v0.z + v1.x + v1.z;
            float W1 = v0.y + v0.w + v1.y + v1.w;
            float F0 = W0 / S0, F1 = W1 / S1;
            out[px] = fmaf(f, F1 - F0, F0);
        }
    }
}

extern "C" void kernel_launch(void* const* d_in, const int* in_sizes, int n_in,
                              void* d_out, int out_size) {
    const float* gt  = (const float*)d_in[0];
    const float* Mod = (const float*)d_in[1];
    const float* Dem = (const float*)d_in[2];
    float* out = (float*)d_out;

    corr_kernel<<<NBLK2, 128>>>(Mod, Dem);

    int smem = 98304;   // templates 80.4KB; 148 blocks -> 1/SM, spin-sync residency
    cudaFuncSetAttribute(tail_kernel, cudaFuncAttributeMaxDynamicSharedMemorySize, smem);
    tail_kernel<<<NBLK, 1024, smem>>>(gt, out);
}